// round 10
// baseline (speedup 1.0000x reference)
#include <cuda_runtime.h>

#define BB 64
#define CC 512
#define TT 16
#define HWD 196
#define KK 8
#define CPB 2                       // slabs per unit (both phases)
#define UPB 256                     // units per batch per phase (512/CPB)
#define SLOTS (BB + 2)              // 66: slot s = pool(s) then gather(s-2)
#define WTOT (SLOTS * 512)          // 33792 units
#define WTICK (WTOT / 2)            // 16896 tickets (2 units each)

// [b][t][c] per-channel partial scores
__device__ float    g_partial[BB * TT * CC];
// [b][t] -> output slot (0-7 approx pos, 8-15 = 8+detail pos)
__device__ int      g_dest[BB * TT];
// per-batch pool completion (exactly 256 adds per launch -> modulo-safe)
__device__ unsigned g_pcnt[BB];
// per-batch selection-done epoch (exactly +1 per launch)
__device__ unsigned g_fin[BB];
// global ticket (exactly WTICK + gridDim adds per launch)
__device__ unsigned g_ticket;

__global__ __launch_bounds__(256) void k_fused(const float* __restrict__ x,
                                               float* __restrict__ out) {
    __shared__ float    pooled[CPB * TT * 49];   // 1568
    __shared__ float    sc[CPB * 49];            // 98
    __shared__ float    v[TT];
    __shared__ int      fa[TT], fd[TT], dst_slot[TT];
    __shared__ unsigned tk[2];
    __shared__ int      sm_sel;

    const unsigned N = gridDim.x;
    const unsigned MODW = WTICK + N;
    const float4* __restrict__ src4 = (const float4*)x;
    float4* __restrict__ out4 = (float4*)out;

    if (threadIdx.x == 0) tk[0] = atomicAdd(&g_ticket, 1u);
    __syncthreads();
    int kb = 0;

    for (;;) {
        const unsigned t = tk[kb];
        const unsigned w = t % MODW;
        if (w >= WTICK) break;                     // terminal: 1 per block per launch
        const unsigned E = t / MODW + 1u;          // launch epoch
        if (threadIdx.x == 0)                      // prefetch next ticket (latency hidden)
            tk[kb ^ 1] = atomicAdd(&g_ticket, 1u);

        #pragma unroll
        for (int half = 0; half < 2; half++) {
            const unsigned u = 2u * w + (unsigned)half;
            const unsigned s = u >> 9;
            const unsigned r = u & 511u;

            if (r < UPB && s < BB) {
                // ======================= pool unit =======================
                const int b   = (int)s;
                const int bc0 = b * CC + (int)r * CPB;
                const float* __restrict__ base = x + (size_t)bc0 * (TT * HWD);

                if (threadIdx.x < CPB * TT * 7) {          // 224 strips
                    int st = threadIdx.x;
                    int ch = st / 112;
                    int q  = st - ch * 112;
                    int tt = q / 7;
                    int y  = q - tt * 7;                   // rows 2y,2y+1
                    const float4* __restrict__ sp =
                        (const float4*)(base + (ch * TT + tt) * HWD + y * 28);
                    float4 r0 = sp[0], r1 = sp[1], r2 = sp[2], r3 = sp[3];
                    float4 r4 = sp[4], r5 = sp[5], r6 = sp[6];
                    float* d = pooled + (ch * TT + tt) * 49 + y * 7;
                    d[0] = 0.25f * (r0.x + r0.y + r3.z + r3.w);
                    d[1] = 0.25f * (r0.z + r0.w + r4.x + r4.y);
                    d[2] = 0.25f * (r1.x + r1.y + r4.z + r4.w);
                    d[3] = 0.25f * (r1.z + r1.w + r5.x + r5.y);
                    d[4] = 0.25f * (r2.x + r2.y + r5.z + r5.w);
                    d[5] = 0.25f * (r2.z + r2.w + r6.x + r6.y);
                    d[6] = 0.25f * (r3.x + r3.y + r6.z + r6.w);
                }
                __syncthreads();

                if (threadIdx.x < CPB * 49) {              // 98 column sums
                    int ch = threadIdx.x / 49, blk = threadIdx.x - ch * 49;
                    const float* pc = pooled + ch * (TT * 49) + blk;
                    float ssum = 0.f;
                    #pragma unroll
                    for (int tt = 0; tt < TT; tt++) ssum += pc[tt * 49];
                    sc[threadIdx.x] = ssum;
                }
                __syncthreads();

                {
                    const int ch = threadIdx.x >> 7;
                    const int tt = (threadIdx.x >> 3) & 15;
                    const int g  = threadIdx.x & 7;
                    const float* pr = pooled + ch * (TT * 49) + tt * 49;
                    const float* sr = sc + ch * 49;
                    float acc = 0.f;
                    #pragma unroll
                    for (int blk = g; blk < 49; blk += 8)
                        acc += pr[blk] * sr[blk];
                    acc += __shfl_xor_sync(0xffffffffu, acc, 4);
                    acc += __shfl_xor_sync(0xffffffffu, acc, 2);
                    acc += __shfl_xor_sync(0xffffffffu, acc, 1);
                    if (g == 0) {
                        int bc = bc0 + ch;
                        g_partial[(b * TT + tt) * CC + (bc & (CC - 1))] = acc;
                    }
                    __threadfence();                       // publish partials
                }

                if (threadIdx.x == 0) {
                    unsigned pc = atomicAdd(&g_pcnt[b], 1u);
                    sm_sel = ((pc & 255u) == 255u);        // last of 256 this launch
                }
                __syncthreads();

                if (sm_sel) {                              // this block selects batch b
                    {
                        int tt = threadIdx.x >> 4, g = threadIdx.x & 15;
                        const float* __restrict__ pp = g_partial + (b * TT + tt) * CC;
                        float ssum = 0.f;
                        #pragma unroll
                        for (int j = 0; j < CC / 16; j++) ssum += __ldcg(&pp[g + 16 * j]);
                        ssum += __shfl_xor_sync(0xffffffffu, ssum, 8);
                        ssum += __shfl_xor_sync(0xffffffffu, ssum, 4);
                        ssum += __shfl_xor_sync(0xffffffffu, ssum, 2);
                        ssum += __shfl_xor_sync(0xffffffffu, ssum, 1);
                        if (g == 0)
                            v[tt] = ssum * (1.0f / (float)(CC * TT))
                                  + ((tt & 1) == 0 ? 1.0f : 0.0f);
                    }
                    __syncthreads();
                    if (threadIdx.x < TT) {                // jax top_k tie semantics
                        const int i = threadIdx.x;
                        const float mv = v[i];
                        int ra = 0, rd = 0;
                        #pragma unroll
                        for (int j = 0; j < TT; j++) {
                            float vj = v[j];
                            ra += (vj > mv) || (vj == mv && j < i);
                            rd += (vj < mv) || (vj == mv && j < i);
                        }
                        fa[i] = (ra < KK);
                        fd[i] = (rd < KK);
                    }
                    __syncthreads();
                    if (threadIdx.x < TT) {
                        const int i = threadIdx.x;
                        int pa = 0, pd = 0;
                        for (int j = 0; j < i; j++) { pa += fa[j]; pd += fd[j]; }
                        g_dest[b * TT + i] = fa[i] ? pa : (KK + pd);  // exactly one set
                        __threadfence();                   // publish dest
                    }
                    __syncthreads();
                    if (threadIdx.x == 0)
                        atomicAdd(&g_fin[b], 1u);          // epoch b -> E
                }
            } else if (r >= UPB && s >= 2) {
                // ====================== gather unit ======================
                const int b  = (int)s - 2;
                const int c0 = (int)(r - UPB) * CPB;

                if (threadIdx.x == 0) {
                    while ((int)(*(volatile unsigned*)&g_fin[b] - E) < 0)
                        __nanosleep(64);
                }
                __syncthreads();
                if (threadIdx.x < TT)
                    dst_slot[threadIdx.x] = __ldcg(&g_dest[b * TT + threadIdx.x]);
                __syncthreads();

                for (int i = threadIdx.x; i < CPB * TT * 49; i += 256) {
                    int cl  = i / 784;
                    int rr  = i - cl * 784;
                    int tt  = rr / 49;
                    int hw4 = rr - tt * 49;
                    float4 val = __ldcs(
                        &src4[((size_t)(b * CC + c0 + cl) * TT + tt) * 49 + hw4]);
                    int sl = dst_slot[tt];
                    unsigned hf = (unsigned)sl >> 3;
                    unsigned j  = (unsigned)sl & (KK - 1);
                    size_t o = (size_t)hf * (BB * CC * KK * 49)
                             + ((size_t)(b * CC + c0 + cl) * KK + j) * 49 + hw4;
                    __stcs(&out4[o], val);
                }
            }
            __syncthreads();                               // smem + tk publish
        }
        kb ^= 1;
    }
}

// ---------------------------------------------------------------------------
extern "C" void kernel_launch(void* const* d_in, const int* in_sizes, int n_in,
                              void* d_out, int out_size) {
    const float* x = (const float*)d_in[0];
    float* out = (float*)d_out;

    // Capture-time sizing; deterministic per device, same every call.
    int dev = 0;
    cudaGetDevice(&dev);
    int nsm = 0;
    cudaDeviceGetAttribute(&nsm, cudaDevAttrMultiProcessorCount, dev);
    int bpm = 0;
    cudaOccupancyMaxActiveBlocksPerMultiprocessor(&bpm, k_fused, 256, 0);
    if (bpm < 1) bpm = 1;
    int grid = nsm * bpm;
    if (grid > 2048) grid = 2048;

    k_fused<<<grid, 256>>>(x, out);
}

// round 11
// speedup vs baseline: 1.7528x; 1.7528x over previous
#include <cuda_runtime.h>

#define BB 64
#define CC 512
#define TT 16
#define HWD 196
#define KK 8
#define CPB 2                 // slabs per pool block

// [b][t][c] per-channel partial scores
__device__ float    g_partial[BB * TT * CC];
// [b][t] -> output slot (0-7 = approx pos, 8-15 = 8+detail pos)
__device__ int      g_dest[BB * TT];
// per-batch pool completion (exactly 256 adds per launch -> modulo-safe)
__device__ unsigned g_pcnt[BB];

// ---------------------------------------------------------------------------
// Kernel 1: pool + partial score for 2 slabs (R5 strip loader). The last
// block to finish a batch (modulo-256 counter) computes that batch's scores
// and destination slots. 256 blocks per batch, blocks ascending in bc.
// ---------------------------------------------------------------------------
__global__ __launch_bounds__(256) void k_pool(const float* __restrict__ x) {
    __shared__ float pooled[CPB * TT * 49];   // 1568
    __shared__ float sc[CPB * 49];            // 98
    __shared__ float v[TT];
    __shared__ int   fa[TT], fd[TT];
    __shared__ int   sm_sel;

    const int bc0 = blockIdx.x * CPB;
    const int b   = bc0 >> 9;
    const float* __restrict__ base = x + (size_t)bc0 * (TT * HWD);

    if (threadIdx.x < CPB * TT * 7) {         // 224 strips
        int s  = threadIdx.x;
        int ch = s / 112;
        int q  = s - ch * 112;
        int t  = q / 7;
        int y  = q - t * 7;                   // pool row (input rows 2y,2y+1)
        const float4* __restrict__ sp =
            (const float4*)(base + (ch * TT + t) * HWD + y * 28);
        float4 r0 = sp[0], r1 = sp[1], r2 = sp[2], r3 = sp[3];
        float4 r4 = sp[4], r5 = sp[5], r6 = sp[6];
        float* d = pooled + (ch * TT + t) * 49 + y * 7;
        d[0] = 0.25f * (r0.x + r0.y + r3.z + r3.w);
        d[1] = 0.25f * (r0.z + r0.w + r4.x + r4.y);
        d[2] = 0.25f * (r1.x + r1.y + r4.z + r4.w);
        d[3] = 0.25f * (r1.z + r1.w + r5.x + r5.y);
        d[4] = 0.25f * (r2.x + r2.y + r5.z + r5.w);
        d[5] = 0.25f * (r2.z + r2.w + r6.x + r6.y);
        d[6] = 0.25f * (r3.x + r3.y + r6.z + r6.w);
    }
    __syncthreads();

    if (threadIdx.x < CPB * 49) {             // 98 column sums
        int ch = threadIdx.x / 49, blk = threadIdx.x - ch * 49;
        const float* pc = pooled + ch * (TT * 49) + blk;
        float s = 0.f;
        #pragma unroll
        for (int t = 0; t < TT; t++) s += pc[t * 49];
        sc[threadIdx.x] = s;
    }
    __syncthreads();

    {
        const int ch = threadIdx.x >> 7;
        const int t  = (threadIdx.x >> 3) & 15;
        const int g  = threadIdx.x & 7;
        const float* pr = pooled + ch * (TT * 49) + t * 49;
        const float* sr = sc + ch * 49;
        float acc = 0.f;
        #pragma unroll
        for (int blk = g; blk < 49; blk += 8)
            acc += pr[blk] * sr[blk];
        acc += __shfl_xor_sync(0xffffffffu, acc, 4);
        acc += __shfl_xor_sync(0xffffffffu, acc, 2);
        acc += __shfl_xor_sync(0xffffffffu, acc, 1);
        if (g == 0) {
            int bc = bc0 + ch;
            g_partial[(b * TT + t) * CC + (bc & (CC - 1))] = acc;
            __threadfence();                  // publish this block's partials
        }
    }
    __syncthreads();

    // last of the 256 blocks of batch b performs selection
    if (threadIdx.x == 0) {
        __threadfence();
        unsigned pc = atomicAdd(&g_pcnt[b], 1u);
        sm_sel = ((pc & 255u) == 255u);
    }
    __syncthreads();
    if (!sm_sel) return;

    {
        int t = threadIdx.x >> 4, g = threadIdx.x & 15;
        const float* __restrict__ pp = g_partial + (b * TT + t) * CC;
        float s = 0.f;
        #pragma unroll
        for (int j = 0; j < CC / 16; j++) s += __ldcg(&pp[g + 16 * j]);
        s += __shfl_xor_sync(0xffffffffu, s, 8);
        s += __shfl_xor_sync(0xffffffffu, s, 4);
        s += __shfl_xor_sync(0xffffffffu, s, 2);
        s += __shfl_xor_sync(0xffffffffu, s, 1);
        if (g == 0)
            v[t] = s * (1.0f / (float)(CC * TT)) + ((t & 1) == 0 ? 1.0f : 0.0f);
    }
    __syncthreads();
    if (threadIdx.x < TT) {                   // jax top_k tie semantics
        const int i = threadIdx.x;
        const float mv = v[i];
        int ra = 0, rd = 0;
        #pragma unroll
        for (int j = 0; j < TT; j++) {
            float vj = v[j];
            ra += (vj > mv) || (vj == mv && j < i);
            rd += (vj < mv) || (vj == mv && j < i);
        }
        fa[i] = (ra < KK);
        fd[i] = (rd < KK);
    }
    __syncthreads();
    if (threadIdx.x < TT) {
        const int i = threadIdx.x;
        int pa = 0, pd = 0;
        for (int j = 0; j < i; j++) { pa += fa[j]; pd += fd[j]; }
        // ranks form a permutation (ra+rd==15): exactly one of fa/fd is set
        g_dest[b * TT + i] = fa[i] ? pa : (KK + pd);
    }
}

// ---------------------------------------------------------------------------
// Kernel 2: gather, walking the input in DESCENDING address order so it first
// consumes the batches k_pool streamed last — those lines are still in L2
// (L2 persists across kernel launches; only L1 is flushed). __ldcs/__stcs
// (evict-first) keep the gather from evicting the not-yet-consumed leftovers.
// Writes are permuted frame-granular, fully line-aligned per (b,c,half).
// ---------------------------------------------------------------------------
#define TOTAL4 (BB * CC * TT * (HWD / 4))   // 25,690,112 float4s

__global__ __launch_bounds__(256) void k_gather(const float* __restrict__ x,
                                                float* __restrict__ out) {
    unsigned i = blockIdx.x * 256 + threadIdx.x;
    if (i >= TOTAL4) return;
    unsigned rev = (TOTAL4 - 1u) - i;         // descending over the input
    float4 val = __ldcs(&((const float4*)x)[rev]);
    unsigned hw4 = rev % 49u;
    unsigned r = rev / 49u;
    unsigned t = r & (TT - 1);
    unsigned c = (r >> 4) & (CC - 1);
    unsigned b = r >> 13;
    int s = __ldg(&g_dest[b * TT + t]);
    unsigned half = (unsigned)s >> 3;
    unsigned j = (unsigned)s & (KK - 1);
    unsigned o = half * (BB * CC * KK * 49u) + ((b * CC + c) * KK + j) * 49u + hw4;
    __stcs(&((float4*)out)[o], val);
}

// ---------------------------------------------------------------------------
extern "C" void kernel_launch(void* const* d_in, const int* in_sizes, int n_in,
                              void* d_out, int out_size) {
    const float* x = (const float*)d_in[0];
    float* out = (float*)d_out;

    k_pool<<<(BB * CC) / CPB, 256>>>(x);
    k_gather<<<TOTAL4 / 256, 256>>>(x, out);
}